// round 10
// baseline (speedup 1.0000x reference)
#include <cuda_runtime.h>
#include <cuda_fp16.h>
#include <cstdint>

// Problem constants
#define B_DIM   512
#define QB      128             // batch rows per quarter
#define IN_DIM  65536
#define OUT_DIM 16384
#define K_DIM   32
#define OTILE   8

#define TBLK_Q  2048            // transpose tiles per quarter
#define GBLK_Q  2048            // gather blocks per quarter
#define GRID_WORK (4 * TBLK_Q + 4 * GBLK_Q)    // 16384
#define GRID_TOTAL (GRID_WORK + 1)             // +1 cleanup block

// 64 MB scratch for transposed x in fp16: xt[in][b]
__device__ __half g_xt_h[(size_t)IN_DIM * B_DIM];

// Gating state. Zero-initialized at load; the cleanup block re-zeroes at the
// end of every kernel execution so each graph replay starts clean.
__device__ int g_tdone[4];
__device__ int g_gpassed;

// Bit-reinterpretation helpers
__device__ __forceinline__ unsigned int h2_to_u32(__half2 h) {
    union { __half2 h; unsigned int u; } c; c.h = h; return c.u;
}
__device__ __forceinline__ float2 u32_to_f2(unsigned int u) {
    union { unsigned int u; __half2 h; } c; c.u = u;
    return __half22float2(c.h);
}

// Shared-memory shapes (union -> fused footprint = max, not sum)
struct SmemT {
    float4 tile4[32][33];                      // 16.9 KB
};
struct SmemG {
    int4   sidx4[OTILE][K_DIM / 4];
    float4 sw4[OTILE][K_DIM / 4];
    float  sbias[OTILE];
    float  sout[OTILE][QB + 8];
};
union SmemU { SmemT t; SmemG g; };

// ---------------------------------------------------------------------------
// Transpose tile body: 32 b-rows x 128 in-cols of x -> fp16 xt.
// Arrives on g_tdone[q] when its gmem stores are visible.
// ---------------------------------------------------------------------------
__device__ __forceinline__ void transpose_tile(
    const float* __restrict__ x, int in0, int b0, int q, SmemT& s)
{
    const int t = threadIdx.x;

    const int c4 = t & 31;
    const int r0 = t >> 5;
    #pragma unroll
    for (int it = 0; it < 4; it++) {
        const int r = r0 + 8 * it;
        s.tile4[r][c4] =
            *(const float4*)&x[(size_t)(b0 + r) * IN_DIM + in0 + 4 * c4];
    }
    __syncthreads();

    const int i = t >> 1;                      // in-row 0..127
    const int p = t & 1;                       // b-chunk (16 b = 32B)
    const int c  = i >> 2;
    const int cc = i & 3;

    __half2 h2[8];
    #pragma unroll
    for (int j = 0; j < 8; j++) {
        const float f0 = ((const float*)&s.tile4[16 * p + 2 * j + 0][c])[cc];
        const float f1 = ((const float*)&s.tile4[16 * p + 2 * j + 1][c])[cc];
        h2[j] = __floats2half2_rn(f0, f1);
    }
    uint4 u0, u1;
    u0.x = h2_to_u32(h2[0]); u0.y = h2_to_u32(h2[1]);
    u0.z = h2_to_u32(h2[2]); u0.w = h2_to_u32(h2[3]);
    u1.x = h2_to_u32(h2[4]); u1.y = h2_to_u32(h2[5]);
    u1.z = h2_to_u32(h2[6]); u1.w = h2_to_u32(h2[7]);

    uint4* dst = (uint4*)&g_xt_h[(size_t)(in0 + i) * B_DIM + b0 + 16 * p];
    dst[0] = u0;
    dst[1] = u1;

    __syncthreads();
    if (t == 0) {
        __threadfence();                       // release stores
        atomicAdd(&g_tdone[q], 1);
    }
}

// ---------------------------------------------------------------------------
// Gather block body: 8 outputs x one b-quarter. Warp per output; lane owns
// 4 b-rows via one LDG.64 per (o,k) -> 256B contiguous column reads.
// Gates on g_tdone[q] before touching xt; reports pass via g_gpassed.
// ---------------------------------------------------------------------------
__device__ __forceinline__ void gather_block(
    const int*   __restrict__ idx,
    const float* __restrict__ w,
    const float* __restrict__ bias,
    float*       __restrict__ out,
    int q, int o0, SmemG& s)
{
    const int tid = threadIdx.x;
    const int wo  = tid >> 5;
    const int l   = tid & 31;

    // Stage idx/w/bias first (overlaps with the wait below)
    if (tid < 64) {
        s.sidx4[tid >> 3][tid & 7] =
            ((const int4*)idx)[(size_t)(o0 + (tid >> 3)) * 8 + (tid & 7)];
    } else if (tid < 128) {
        const int u = tid - 64;
        s.sw4[u >> 3][u & 7] =
            ((const float4*)w)[(size_t)(o0 + (u >> 3)) * 8 + (u & 7)];
    } else if (tid < 128 + OTILE) {
        s.sbias[tid - 128] = bias[o0 + (tid - 128)];
    }

    // Acquire: wait until this quarter's transpose fully arrived.
    if (tid == 0) {
        while (*(volatile int*)&g_tdone[q] < TBLK_Q) __nanosleep(64);
        __threadfence();
        atomicAdd(&g_gpassed, 1);              // cleanup bookkeeping
    }
    __syncthreads();

    // xt row = 512 halves = 128 uint2 slots; quarter q = slots [32q, 32q+32).
    const uint2* __restrict__ xt8 =
        reinterpret_cast<const uint2*>(g_xt_h) + (size_t)q * 32 + l;

    float a0 = 0.f, a1 = 0.f, a2 = 0.f, a3 = 0.f;

    #pragma unroll
    for (int k4 = 0; k4 < K_DIM / 4; k4++) {
        const int4   ii = s.sidx4[wo][k4];
        const float4 ww = s.sw4[wo][k4];
        const uint2 v0 = __ldg(&xt8[(size_t)ii.x * 128]);
        const uint2 v1 = __ldg(&xt8[(size_t)ii.y * 128]);
        const uint2 v2 = __ldg(&xt8[(size_t)ii.z * 128]);
        const uint2 v3 = __ldg(&xt8[(size_t)ii.w * 128]);

        {
            const float2 f0 = u32_to_f2(v0.x), f1 = u32_to_f2(v0.y);
            a0 += f0.x * ww.x; a1 += f0.y * ww.x;
            a2 += f1.x * ww.x; a3 += f1.y * ww.x;
        }
        {
            const float2 f0 = u32_to_f2(v1.x), f1 = u32_to_f2(v1.y);
            a0 += f0.x * ww.y; a1 += f0.y * ww.y;
            a2 += f1.x * ww.y; a3 += f1.y * ww.y;
        }
        {
            const float2 f0 = u32_to_f2(v2.x), f1 = u32_to_f2(v2.y);
            a0 += f0.x * ww.z; a1 += f0.y * ww.z;
            a2 += f1.x * ww.z; a3 += f1.y * ww.z;
        }
        {
            const float2 f0 = u32_to_f2(v3.x), f1 = u32_to_f2(v3.y);
            a0 += f0.x * ww.w; a1 += f0.y * ww.w;
            a2 += f1.x * ww.w; a3 += f1.y * ww.w;
        }
    }

    const float bv = s.sbias[wo];
    float4 sv = make_float4(a0 + bv, a1 + bv, a2 + bv, a3 + bv);
    *(float4*)&s.sout[wo][4 * l] = sv;         // warp: contiguous STS.128
    __syncthreads();

    if (tid < QB) {
        const int b = q * QB + tid;
        float4 r0, r1;
        r0.x = s.sout[0][tid]; r0.y = s.sout[1][tid];
        r0.z = s.sout[2][tid]; r0.w = s.sout[3][tid];
        r1.x = s.sout[4][tid]; r1.y = s.sout[5][tid];
        r1.z = s.sout[6][tid]; r1.w = s.sout[7][tid];
        float4* dst = reinterpret_cast<float4*>(out + (size_t)b * OUT_DIM + o0);
        dst[0] = r0;
        dst[1] = r1;
    }
}

// ---------------------------------------------------------------------------
// Mega kernel: quarter pipeline via static bid partition.
//   [0,2048):        T(q0)
//   [2048,6144):     1:1  G(q0) : T(q1)
//   [6144,10240):    1:1  G(q1) : T(q2)
//   [10240,14336):   1:1  G(q2) : T(q3)
//   [14336,16384):   G(q3)
//   16384:           cleanup (waits for all G gates passed, zeroes counters)
// Deadlock-free: every T(q) bid precedes every G(q) bid; CTAs are claimed in
// bid order, so gated counters always reach TBLK_Q.
// ---------------------------------------------------------------------------
__global__ __launch_bounds__(256) void mega_kernel(
    const float* __restrict__ x,
    const int*   __restrict__ idx,
    const float* __restrict__ w,
    const float* __restrict__ bias,
    float*       __restrict__ out)
{
    __shared__ SmemU sm;
    const int bx = blockIdx.x;

    if (bx < TBLK_Q) {
        const int j = bx;
        transpose_tile(x, (j & 511) << 7, (j >> 9) * 32, 0, sm.t);
    } else if (bx < TBLK_Q + 3 * (TBLK_Q + GBLK_Q)) {
        const int r     = bx - TBLK_Q;
        const int phase = r >> 12;             // / 4096
        const int off   = r & 4095;
        const int j     = off >> 1;
        if (off & 1) {
            const int q = phase + 1;
            transpose_tile(x, (j & 511) << 7, q * QB + (j >> 9) * 32, q, sm.t);
        } else {
            gather_block(idx, w, bias, out, phase, j * OTILE, sm.g);
        }
    } else if (bx < GRID_WORK) {
        const int j = bx - (TBLK_Q + 3 * (TBLK_Q + GBLK_Q));
        gather_block(idx, w, bias, out, 3, j * OTILE, sm.g);
    } else {
        // Cleanup: after every gather block has passed its gate, no one reads
        // the counters again -> safe to zero them for the next replay.
        if (threadIdx.x == 0) {
            while (*(volatile int*)&g_gpassed < 4 * GBLK_Q) __nanosleep(128);
            g_tdone[0] = 0; g_tdone[1] = 0;
            g_tdone[2] = 0; g_tdone[3] = 0;
            g_gpassed  = 0;
        }
    }
}

// ---------------------------------------------------------------------------
// Launch: one kernel, no reset launch (self-resetting).
// ---------------------------------------------------------------------------
extern "C" void kernel_launch(void* const* d_in, const int* in_sizes, int n_in,
                              void* d_out, int out_size) {
    const float* x    = (const float*)d_in[0];
    const int*   idx  = (const int*)  d_in[1];
    const float* w    = (const float*)d_in[2];
    const float* bias = (const float*)d_in[3];
    float*       out  = (float*)d_out;

    mega_kernel<<<GRID_TOTAL, 256>>>(x, idx, w, bias, out);
}